// round 1
// baseline (speedup 1.0000x reference)
#include <cuda_runtime.h>
#include <cstdint>
#include <cmath>

// Problem constants
#define TQ   4096          // sequence length
#define DM   1024          // d_model
#define NH   16            // heads
#define DH   64            // head dim

// Scratch (allocation-free rule: __device__ globals)
__device__ float g_qkv[(size_t)TQ * 3 * DM];   // [t][3c]  (q | k | v)
__device__ float g_att[(size_t)TQ * DM];       // attention output [t][c]

// ---------------------------------------------------------------------------
// tf32 helpers
// ---------------------------------------------------------------------------
__device__ __forceinline__ unsigned f2tf(float x) {
    unsigned u;
    asm("cvt.rna.tf32.f32 %0, %1;" : "=r"(u) : "f"(x));
    return u;
}

__device__ __forceinline__ void mma_tf32(float* d, const unsigned* a,
                                         unsigned b0, unsigned b1) {
    asm volatile(
        "mma.sync.aligned.m16n8k8.row.col.f32.tf32.tf32.f32 "
        "{%0,%1,%2,%3}, {%4,%5,%6,%7}, {%8,%9}, {%0,%1,%2,%3};\n"
        : "+f"(d[0]), "+f"(d[1]), "+f"(d[2]), "+f"(d[3])
        : "r"(a[0]), "r"(a[1]), "r"(a[2]), "r"(a[3]), "r"(b0), "r"(b1));
}

// ---------------------------------------------------------------------------
// Tiled tf32 GEMM: C[M,N] = A[M,K] @ B[K,N], all row-major fp32.
// BM=128, BN=128, BK=16, 256 threads (8 warps: 4 along M x 2 along N,
// warp tile 32x64 = 2 x 8 mma tiles of m16n8k8).
// ---------------------------------------------------------------------------
__global__ __launch_bounds__(256) void gemm_tf32(const float* __restrict__ A,
                                                 const float* __restrict__ B,
                                                 float* __restrict__ C,
                                                 int M, int N, int K)
{
    __shared__ float As[128 * 20];   // pad to 20: conflict-free a-frag loads
    __shared__ float Bs[16 * 132];   // pad to 132

    const int tid  = threadIdx.x;
    const int lane = tid & 31;
    const int warp = tid >> 5;
    const int wm   = warp & 3;       // 4 warps along M (32 rows each)
    const int wn   = warp >> 2;      // 2 warps along N (64 cols each)
    const int bx   = blockIdx.x;     // N block
    const int by   = blockIdx.y;     // M block
    const int g    = lane >> 2;      // group row 0..7
    const int tc   = lane & 3;       // thread col 0..3

    float acc[2][8][4];
#pragma unroll
    for (int mt = 0; mt < 2; mt++)
#pragma unroll
        for (int nt = 0; nt < 8; nt++)
#pragma unroll
            for (int j = 0; j < 4; j++) acc[mt][nt][j] = 0.f;

    const float* Ablk = A + (size_t)by * 128 * K;
    const float* Bblk = B + (size_t)bx * 128;

    for (int kt = 0; kt < K; kt += 16) {
        __syncthreads();
        // ---- load A tile 128x16 (fp32 -> tf32) ----
#pragma unroll
        for (int i = 0; i < 2; i++) {
            int lid = tid + i * 256;              // 0..511
            int r   = lid >> 2;
            int c4  = (lid & 3) * 4;
            float4 v = *(const float4*)(Ablk + (size_t)r * K + kt + c4);
            float4 w;
            w.x = __uint_as_float(f2tf(v.x));
            w.y = __uint_as_float(f2tf(v.y));
            w.z = __uint_as_float(f2tf(v.z));
            w.w = __uint_as_float(f2tf(v.w));
            *(float4*)(As + r * 20 + c4) = w;
        }
        // ---- load B tile 16x128 ----
#pragma unroll
        for (int i = 0; i < 2; i++) {
            int lid = tid + i * 256;
            int kr  = lid >> 5;                   // 0..15
            int c4  = (lid & 31) * 4;             // 0..124
            float4 v = *(const float4*)(Bblk + (size_t)(kt + kr) * N + c4);
            float4 w;
            w.x = __uint_as_float(f2tf(v.x));
            w.y = __uint_as_float(f2tf(v.y));
            w.z = __uint_as_float(f2tf(v.z));
            w.w = __uint_as_float(f2tf(v.w));
            *(float4*)(Bs + kr * 132 + c4) = w;
        }
        __syncthreads();

#pragma unroll
        for (int ks = 0; ks < 2; ks++) {
            unsigned a[2][4];
#pragma unroll
            for (int mt = 0; mt < 2; mt++) {
                int row = wm * 32 + mt * 16 + g;
                int col = ks * 8 + tc;
                a[mt][0] = __float_as_uint(As[row * 20 + col]);
                a[mt][1] = __float_as_uint(As[(row + 8) * 20 + col]);
                a[mt][2] = __float_as_uint(As[row * 20 + col + 4]);
                a[mt][3] = __float_as_uint(As[(row + 8) * 20 + col + 4]);
            }
#pragma unroll
            for (int nt = 0; nt < 8; nt++) {
                int nc = wn * 64 + nt * 8 + g;
                unsigned b0 = __float_as_uint(Bs[(ks * 8 + tc) * 132 + nc]);
                unsigned b1 = __float_as_uint(Bs[(ks * 8 + tc + 4) * 132 + nc]);
                mma_tf32(acc[0][nt], a[0], b0, b1);
                mma_tf32(acc[1][nt], a[1], b0, b1);
            }
        }
    }

    // ---- epilogue ----
#pragma unroll
    for (int mt = 0; mt < 2; mt++)
#pragma unroll
        for (int nt = 0; nt < 8; nt++) {
            int r0 = by * 128 + wm * 32 + mt * 16 + g;
            int c0 = bx * 128 + wn * 64 + nt * 8 + 2 * tc;
            *(float2*)(C + (size_t)r0 * N + c0) =
                make_float2(acc[mt][nt][0], acc[mt][nt][1]);
            *(float2*)(C + (size_t)(r0 + 8) * N + c0) =
                make_float2(acc[mt][nt][2], acc[mt][nt][3]);
        }
}

// ---------------------------------------------------------------------------
// Causal flash attention, tf32 mma.
// Grid: (64 q-tiles, 16 heads). Block: 128 threads (4 warps), each warp owns
// 16 q-rows. KV tiles of 64 iterated 0..qt (causal skip). Online softmax.
// Dynamic smem: Qs | Ks | Vs | Ps, each 64 rows x 68 floats (padded).
// ---------------------------------------------------------------------------
#define ROWP 68
__global__ __launch_bounds__(128) void attn_fwd()
{
    extern __shared__ float sm[];
    float* Qs = sm;
    float* Ks = Qs + 64 * ROWP;
    float* Vs = Ks + 64 * ROWP;
    float* Ps = Vs + 64 * ROWP;

    const int tid  = threadIdx.x;
    const int lane = tid & 31;
    const int warp = tid >> 5;
    const int h    = blockIdx.y;
    const int qt   = (int)gridDim.x - 1 - (int)blockIdx.x;  // big tiles first
    const int q0   = qt * 64;
    const int g    = lane >> 2;
    const int tc   = lane & 3;

    // ---- load Q tile (scale 1/sqrt(dh) folded in) ----
#pragma unroll
    for (int i = 0; i < 8; i++) {
        int lid = tid + i * 128;            // 0..1023 float4s
        int r   = lid >> 4;
        int c4  = (lid & 15) * 4;
        float4 v = *(const float4*)(g_qkv + (size_t)(q0 + r) * (3 * DM) + h * DH + c4);
        float4 w;
        w.x = __uint_as_float(f2tf(v.x * 0.125f));
        w.y = __uint_as_float(f2tf(v.y * 0.125f));
        w.z = __uint_as_float(f2tf(v.z * 0.125f));
        w.w = __uint_as_float(f2tf(v.w * 0.125f));
        *(float4*)(Qs + r * ROWP + c4) = w;
    }

    float o[8][4];
#pragma unroll
    for (int nt = 0; nt < 8; nt++)
#pragma unroll
        for (int j = 0; j < 4; j++) o[nt][j] = 0.f;
    float mA = -INFINITY, mB = -INFINITY, lA = 0.f, lB = 0.f;

    for (int t = 0; t <= qt; t++) {
        __syncthreads();   // previous iteration done with Ks/Vs (also covers Qs init)
        // ---- load K, V tiles ----
#pragma unroll
        for (int i = 0; i < 8; i++) {
            int lid = tid + i * 128;
            int r   = lid >> 4;
            int c4  = (lid & 15) * 4;
            const float* kp = g_qkv + (size_t)(t * 64 + r) * (3 * DM) + DM + h * DH + c4;
            const float* vp = g_qkv + (size_t)(t * 64 + r) * (3 * DM) + 2 * DM + h * DH + c4;
            float4 kv = *(const float4*)kp;
            float4 vv = *(const float4*)vp;
            float4 kw, vw;
            kw.x = __uint_as_float(f2tf(kv.x)); kw.y = __uint_as_float(f2tf(kv.y));
            kw.z = __uint_as_float(f2tf(kv.z)); kw.w = __uint_as_float(f2tf(kv.w));
            vw.x = __uint_as_float(f2tf(vv.x)); vw.y = __uint_as_float(f2tf(vv.y));
            vw.z = __uint_as_float(f2tf(vv.z)); vw.w = __uint_as_float(f2tf(vv.w));
            *(float4*)(Ks + r * ROWP + c4) = kw;
            *(float4*)(Vs + r * ROWP + c4) = vw;
        }
        __syncthreads();

        // ---- S = (Q*scale) @ K^T : warp computes 16 x 64 ----
        float s[8][4];
#pragma unroll
        for (int nt = 0; nt < 8; nt++)
#pragma unroll
            for (int j = 0; j < 4; j++) s[nt][j] = 0.f;

#pragma unroll
        for (int ks = 0; ks < 8; ks++) {
            unsigned a[4];
            int row = warp * 16 + g;
            int col = ks * 8 + tc;
            a[0] = __float_as_uint(Qs[row * ROWP + col]);
            a[1] = __float_as_uint(Qs[(row + 8) * ROWP + col]);
            a[2] = __float_as_uint(Qs[row * ROWP + col + 4]);
            a[3] = __float_as_uint(Qs[(row + 8) * ROWP + col + 4]);
#pragma unroll
            for (int nt = 0; nt < 8; nt++) {
                int nc = nt * 8 + g;
                unsigned b0 = __float_as_uint(Ks[nc * ROWP + col]);
                unsigned b1 = __float_as_uint(Ks[nc * ROWP + col + 4]);
                mma_tf32(s[nt], a, b0, b1);
            }
        }

        // ---- causal mask on diagonal tile ----
        if (t == qt) {
            int qlA = warp * 16 + g;
            int qlB = qlA + 8;
#pragma unroll
            for (int nt = 0; nt < 8; nt++) {
                int k0 = nt * 8 + 2 * tc;
                if (k0     > qlA) s[nt][0] = -INFINITY;
                if (k0 + 1 > qlA) s[nt][1] = -INFINITY;
                if (k0     > qlB) s[nt][2] = -INFINITY;
                if (k0 + 1 > qlB) s[nt][3] = -INFINITY;
            }
        }

        // ---- online softmax ----
        float rA = -INFINITY, rB = -INFINITY;
#pragma unroll
        for (int nt = 0; nt < 8; nt++) {
            rA = fmaxf(rA, fmaxf(s[nt][0], s[nt][1]));
            rB = fmaxf(rB, fmaxf(s[nt][2], s[nt][3]));
        }
        rA = fmaxf(rA, __shfl_xor_sync(0xffffffffu, rA, 1));
        rA = fmaxf(rA, __shfl_xor_sync(0xffffffffu, rA, 2));
        rB = fmaxf(rB, __shfl_xor_sync(0xffffffffu, rB, 1));
        rB = fmaxf(rB, __shfl_xor_sync(0xffffffffu, rB, 2));

        float mAn = fmaxf(mA, rA), mBn = fmaxf(mB, rB);
        float fA = __expf(mA - mAn), fB = __expf(mB - mBn);

        float sumA = 0.f, sumB = 0.f;
        int rowA = warp * 16 + g;
#pragma unroll
        for (int nt = 0; nt < 8; nt++) {
            float p0 = __uint_as_float(f2tf(__expf(s[nt][0] - mAn)));
            float p1 = __uint_as_float(f2tf(__expf(s[nt][1] - mAn)));
            float p2 = __uint_as_float(f2tf(__expf(s[nt][2] - mBn)));
            float p3 = __uint_as_float(f2tf(__expf(s[nt][3] - mBn)));
            sumA += p0 + p1;
            sumB += p2 + p3;
            int c0 = nt * 8 + 2 * tc;
            Ps[rowA * ROWP + c0]           = p0;
            Ps[rowA * ROWP + c0 + 1]       = p1;
            Ps[(rowA + 8) * ROWP + c0]     = p2;
            Ps[(rowA + 8) * ROWP + c0 + 1] = p3;
        }
        sumA += __shfl_xor_sync(0xffffffffu, sumA, 1);
        sumA += __shfl_xor_sync(0xffffffffu, sumA, 2);
        sumB += __shfl_xor_sync(0xffffffffu, sumB, 1);
        sumB += __shfl_xor_sync(0xffffffffu, sumB, 2);

        lA = lA * fA + sumA;
        lB = lB * fB + sumB;
        mA = mAn; mB = mBn;
#pragma unroll
        for (int nt = 0; nt < 8; nt++) {
            o[nt][0] *= fA; o[nt][1] *= fA;
            o[nt][2] *= fB; o[nt][3] *= fB;
        }
        __syncwarp();   // each warp consumes only its own P rows

        // ---- O += P @ V ----
#pragma unroll
        for (int ks = 0; ks < 8; ks++) {
            unsigned a[4];
            int row = warp * 16 + g;
            int col = ks * 8 + tc;     // kv index
            a[0] = __float_as_uint(Ps[row * ROWP + col]);
            a[1] = __float_as_uint(Ps[(row + 8) * ROWP + col]);
            a[2] = __float_as_uint(Ps[row * ROWP + col + 4]);
            a[3] = __float_as_uint(Ps[(row + 8) * ROWP + col + 4]);
#pragma unroll
            for (int nt = 0; nt < 8; nt++) {
                unsigned b0 = __float_as_uint(Vs[col * ROWP + nt * 8 + g]);
                unsigned b1 = __float_as_uint(Vs[(col + 4) * ROWP + nt * 8 + g]);
                mma_tf32(o[nt], a, b0, b1);
            }
        }
    }

    // ---- epilogue: normalize, write [t][h*64+d] ----
    float invA = 1.f / lA, invB = 1.f / lB;
    int rowA = q0 + warp * 16 + g;
#pragma unroll
    for (int nt = 0; nt < 8; nt++) {
        int c = h * DH + nt * 8 + 2 * tc;
        *(float2*)(g_att + (size_t)rowA * DM + c) =
            make_float2(o[nt][0] * invA, o[nt][1] * invA);
        *(float2*)(g_att + (size_t)(rowA + 8) * DM + c) =
            make_float2(o[nt][2] * invB, o[nt][3] * invB);
    }
}

// ---------------------------------------------------------------------------
// Launch
// ---------------------------------------------------------------------------
extern "C" void kernel_launch(void* const* d_in, const int* in_sizes, int n_in,
                              void* d_out, int out_size)
{
    const float* x      = (const float*)d_in[0];   // [4096,1024]
    const float* w_qkv  = (const float*)d_in[1];   // [1024,3072]
    const float* w_proj = (const float*)d_in[2];   // [1024,1024]
    float* out          = (float*)d_out;           // [4096,1024]

    float* qkv_ptr = nullptr;
    float* att_ptr = nullptr;
    cudaGetSymbolAddress((void**)&qkv_ptr, g_qkv);
    cudaGetSymbolAddress((void**)&att_ptr, g_att);

    const int attn_smem = 4 * 64 * ROWP * (int)sizeof(float);   // 69632
    cudaFuncSetAttribute(attn_fwd, cudaFuncAttributeMaxDynamicSharedMemorySize,
                         attn_smem);

    // 1) QKV projection: [4096,1024] @ [1024,3072] -> g_qkv
    gemm_tf32<<<dim3(3 * DM / 128, TQ / 128), 256>>>(x, w_qkv, qkv_ptr,
                                                     TQ, 3 * DM, DM);
    // 2) causal attention -> g_att
    attn_fwd<<<dim3(TQ / 64, NH), 128, attn_smem>>>();
    // 3) output projection: [4096,1024] @ [1024,1024] -> out
    gemm_tf32<<<dim3(DM / 128, TQ / 128), 256>>>(att_ptr, w_proj, out,
                                                 TQ, DM, DM);
}